// round 5
// baseline (speedup 1.0000x reference)
#include <cuda_runtime.h>
#include <math.h>

// out[i] = F(x[i]) for a fixed smooth scalar F (weights shared across elems).
// Kernel 1: warp-per-entry exact tabulation of F on [-6.5, 6.5] (8192 nodes),
//           stored as overlapping float2 pairs {tab[j], tab[j+1]}.
// Kernel 2: streaming LINEAR interpolation (1 gather/element), x clamped into
//           the domain (x ~ N(0,1): max|x|~5.2 << 6.5; F saturates at edges).

#define HH 20
#define GG 80
#define LN_EPS 1e-5f

#define TAB_N 8192
#define TAB_XMIN (-6.5f)
#define TAB_XMAX (6.5f)
#define TAB_STEP ((TAB_XMAX - TAB_XMIN) / (float)(TAB_N - 1))
#define TAB_INV_STEP ((float)(TAB_N - 1) / (TAB_XMAX - TAB_XMIN))

__device__ float2 g_tab2[TAB_N];   // g_tab2[j] = {tab[j], tab[j+1]}

struct Weights {
    const float *W1, *b1, *g1, *be1;
    const float *Wih0, *gi0, *bi0, *bh0, *go0, *bo0;
    const float *Wih1, *gi1, *bi1, *bh1, *go1, *bo1;
    const float *Wout, *bout;
};

__device__ __forceinline__ float fast_sigmoid(float z) {
    return 1.0f / (1.0f + __expf(-z));
}
__device__ __forceinline__ float fast_tanh(float z) {
    return 1.0f - 2.0f / (1.0f + __expf(2.0f * z));
}
__device__ __forceinline__ float warp_sum(float v) {
#pragma unroll
    for (int off = 16; off; off >>= 1) v += __shfl_xor_sync(0xffffffffu, v, off);
    return v;
}

// ===================== kernel 1: warp-per-entry table build =================
#define BUILD_WARPS 8
#define ENTRIES_PER_WARP 2
#define WPITCH 21
#define WROWS  96

__device__ __forceinline__ float cell_warp(const float* __restrict__ v,
                                           const float* __restrict__ Wsm,
                                           const float* gi, const float* bi,
                                           const float* bh, const float* go,
                                           const float* bo, float* gbuf,
                                           int lane) {
    const bool v2 = lane < 16;
    const bool act = lane < HH;
    const float* w0 = Wsm + lane * WPITCH;
    const float* w1 = Wsm + (32 + lane) * WPITCH;
    const float* w2 = Wsm + (64 + lane) * WPITCH;  // rows >= 80 are zero
    float a0 = 0.f, a1 = 0.f, a2 = 0.f;
#pragma unroll
    for (int k = 0; k < HH; k++) {
        a0 = fmaf(v[k], w0[k], a0);
        a1 = fmaf(v[k], w1[k], a1);
        a2 = fmaf(v[k], w2[k], a2);
    }
    float mu = warp_sum(a0 + a1 + a2) * (1.f / 80.f);
    float d0 = a0 - mu, d1 = a1 - mu, d2 = v2 ? (a2 - mu) : 0.f;
    float var = warp_sum(fmaf(d0, d0, fmaf(d1, d1, d2 * d2))) * (1.f / 79.f);
    float inv = 1.f / (sqrtf(var) + LN_EPS);
    gbuf[lane]      = d0 * inv * gi[lane]      + bi[lane]      + bh[lane];
    gbuf[32 + lane] = d1 * inv * gi[32 + lane] + bi[32 + lane] + bh[32 + lane];
    if (v2)
        gbuf[64 + lane] = d2 * inv * gi[64 + lane] + bi[64 + lane] + bh[64 + lane];
    __syncwarp();
    float c = 0.f, ov = 0.f;
    if (act) {
        float iv = gbuf[lane];
        ov = gbuf[40 + lane];
        float gv = gbuf[60 + lane];
        c = fast_sigmoid(iv) * fast_tanh(gv);
    }
    __syncwarp();
    float mu2 = warp_sum(c) * (1.f / 20.f);
    float dc = act ? (c - mu2) : 0.f;
    float var2 = warp_sum(dc * dc) * (1.f / 19.f);
    float inv2 = 1.f / (sqrtf(var2) + LN_EPS);
    float h = 0.f;
    if (act) {
        float cn = dc * inv2 * go[lane] + bo[lane];
        h = fast_sigmoid(ov) * fast_tanh(cn);
    }
    return h;
}

__global__ void __launch_bounds__(32 * BUILD_WARPS)
build_table_kernel(Weights w) {
    __shared__ float Wih0_s[WROWS * WPITCH];
    __shared__ float Wih1_s[WROWS * WPITCH];
    __shared__ float gates_s[BUILD_WARPS][GG];
    __shared__ float hx_s[BUILD_WARPS][HH];

    int tid = threadIdx.x;
    for (int idx = tid; idx < WROWS * WPITCH; idx += blockDim.x) {
        int r = idx / WPITCH, k = idx - r * WPITCH;
        float v0 = 0.f, v1 = 0.f;
        if (r < GG && k < HH) { v0 = w.Wih0[r * HH + k]; v1 = w.Wih1[r * HH + k]; }
        Wih0_s[idx] = v0;
        Wih1_s[idx] = v1;
    }
    __syncthreads();

    int warp = tid >> 5, lane = tid & 31;
    const bool act = lane < HH;

#pragma unroll
    for (int e = 0; e < ENTRIES_PER_WARP; e++) {
        int entry = (blockIdx.x * BUILD_WARPS + warp) * ENTRIES_PER_WARP + e;
        float x = fmaf((float)entry, TAB_STEP, TAB_XMIN);

        // layer 1
        float hval = 0.f;
        if (act) hval = fmaf(x, w.W1[lane], w.b1[lane]);
        {
            float mu = warp_sum(act ? hval : 0.f) * (1.f / 20.f);
            float d = act ? (hval - mu) : 0.f;
            float var = warp_sum(d * d) * (1.f / 19.f);
            float inv = 1.f / (sqrtf(var) + LN_EPS);
            if (act) hval = fast_tanh(d * inv * w.g1[lane] + w.be1[lane]);
        }

        float v[HH];
        if (act) hx_s[warp][lane] = hval;
        __syncwarp();
#pragma unroll
        for (int k = 0; k < HH; k++) v[k] = hx_s[warp][k];
        __syncwarp();

        hval = cell_warp(v, Wih0_s, w.gi0, w.bi0, w.bh0, w.go0, w.bo0,
                         gates_s[warp], lane);

        if (act) hx_s[warp][lane] = hval;
        __syncwarp();
#pragma unroll
        for (int k = 0; k < HH; k++) v[k] = hx_s[warp][k];
        __syncwarp();

        hval = cell_warp(v, Wih1_s, w.gi1, w.bi1, w.bh1, w.go1, w.bo1,
                         gates_s[warp], lane);

        float p = act ? hval * w.Wout[lane] : 0.f;
        p = warp_sum(p);
        if (lane == 0) {
            float val = p + w.bout[0];
            g_tab2[entry].x = val;
            if (entry > 0) g_tab2[entry - 1].y = val;
            if (entry == TAB_N - 1) g_tab2[entry].y = val;  // defined, never read
        }
    }
}

// ===================== kernel 2: streaming linear interpolation =============
__device__ __forceinline__ float interp_one(float x) {
    x = fminf(fmaxf(x, TAB_XMIN), TAB_XMAX);
    float t = (x - TAB_XMIN) * TAB_INV_STEP;
    int i = __float2int_rd(t);
    i = min(i, TAB_N - 2);
    float s = t - (float)i;
    float2 q = g_tab2[i];                 // {tab[i], tab[i+1]} — one LDG.64
    return fmaf(s, q.y - q.x, q.x);
}

__device__ __forceinline__ float4 interp_vec(float4 xv) {
    float4 ov;
    ov.x = interp_one(xv.x);
    ov.y = interp_one(xv.y);
    ov.z = interp_one(xv.z);
    ov.w = interp_one(xv.w);
    return ov;
}

#define VPT 4   // float4s per thread (front-batched -> MLP=4)

__global__ void __launch_bounds__(256)
interp_kernel(const float4* __restrict__ x4, float4* __restrict__ o4, int n4,
              const float* __restrict__ x, float* __restrict__ out, int n) {
    int base = blockIdx.x * (256 * VPT) + threadIdx.x;

    if (base + (VPT - 1) * 256 < n4) {           // hot: full block, no guards
        float4 xv[VPT];
#pragma unroll
        for (int j = 0; j < VPT; j++) xv[j] = __ldcs(&x4[base + j * 256]);
#pragma unroll
        for (int j = 0; j < VPT; j++) __stcs(&o4[base + j * 256], interp_vec(xv[j]));
    } else {                                      // edge block
#pragma unroll
        for (int j = 0; j < VPT; j++) {
            int idx = base + j * 256;
            if (idx < n4) __stcs(&o4[idx], interp_vec(__ldcs(&x4[idx])));
        }
        // n % 4 tail
        if (blockIdx.x == gridDim.x - 1 && threadIdx.x < 32) {
            for (int i = n4 * 4 + threadIdx.x; i < n; i += 32)
                out[i] = interp_one(x[i]);
        }
    }
}

extern "C" void kernel_launch(void* const* d_in, const int* in_sizes, int n_in,
                              void* d_out, int out_size) {
    Weights w;
    w.W1 = (const float*)d_in[1];
    w.b1 = (const float*)d_in[2];
    w.g1 = (const float*)d_in[3];
    w.be1 = (const float*)d_in[4];
    w.Wih0 = (const float*)d_in[5];
    w.gi0 = (const float*)d_in[7];
    w.bi0 = (const float*)d_in[8];
    w.bh0 = (const float*)d_in[10];
    w.go0 = (const float*)d_in[11];
    w.bo0 = (const float*)d_in[12];
    w.Wih1 = (const float*)d_in[13];
    w.gi1 = (const float*)d_in[15];
    w.bi1 = (const float*)d_in[16];
    w.bh1 = (const float*)d_in[18];
    w.go1 = (const float*)d_in[19];
    w.bo1 = (const float*)d_in[20];
    w.Wout = (const float*)d_in[21];
    w.bout = (const float*)d_in[22];

    const float* x = (const float*)d_in[0];
    float* out = (float*)d_out;
    int n = in_sizes[0];
    int n4 = n / 4;

    int build_blocks = TAB_N / (BUILD_WARPS * ENTRIES_PER_WARP);
    build_table_kernel<<<build_blocks, 32 * BUILD_WARPS>>>(w);

    int per_block = 256 * VPT;
    int blocks = (n4 + per_block - 1) / per_block;
    if (blocks == 0) blocks = 1;
    interp_kernel<<<blocks, 256>>>((const float4*)x, (float4*)out, n4, x, out, n);
}

// round 6
// speedup vs baseline: 1.3072x; 1.3072x over previous
#include <cuda_runtime.h>
#include <math.h>

// out[i] = F(x[i]) for a fixed smooth scalar F (weights shared across elems).
// Kernel 1: warp-per-entry exact tabulation of F on [-6.5, 6.5] (4096 nodes),
//           stored as overlapping float2 pairs {tab[j], tab[j+1]}.
// Kernel 2: streaming LINEAR interpolation with the table staged in SHARED
//           memory (random gathers hit smem banks, not L1 wavefronts).
//           x clamped into the domain (x~N(0,1): max|x|~5.2 << 6.5).

#define HH 20
#define GG 80
#define LN_EPS 1e-5f

#define TAB_N 4096
#define TAB_XMIN (-6.5f)
#define TAB_XMAX (6.5f)
#define TAB_STEP ((TAB_XMAX - TAB_XMIN) / (float)(TAB_N - 1))
#define TAB_INV_STEP ((float)(TAB_N - 1) / (TAB_XMAX - TAB_XMIN))

__device__ float2 g_tab2[TAB_N];   // g_tab2[j] = {tab[j], tab[j+1]}

struct Weights {
    const float *W1, *b1, *g1, *be1;
    const float *Wih0, *gi0, *bi0, *bh0, *go0, *bo0;
    const float *Wih1, *gi1, *bi1, *bh1, *go1, *bo1;
    const float *Wout, *bout;
};

__device__ __forceinline__ float fast_sigmoid(float z) {
    return 1.0f / (1.0f + __expf(-z));
}
__device__ __forceinline__ float fast_tanh(float z) {
    return 1.0f - 2.0f / (1.0f + __expf(2.0f * z));
}
__device__ __forceinline__ float warp_sum(float v) {
#pragma unroll
    for (int off = 16; off; off >>= 1) v += __shfl_xor_sync(0xffffffffu, v, off);
    return v;
}

// ===================== kernel 1: warp-per-entry table build =================
#define BUILD_WARPS 16
#define WPITCH 21
#define WROWS  96

__device__ __forceinline__ float cell_warp(const float* __restrict__ v,
                                           const float* __restrict__ Wsm,
                                           const float* gi, const float* bi,
                                           const float* bh, const float* go,
                                           const float* bo, float* gbuf,
                                           int lane) {
    const bool v2 = lane < 16;
    const bool act = lane < HH;
    const float* w0 = Wsm + lane * WPITCH;
    const float* w1 = Wsm + (32 + lane) * WPITCH;
    const float* w2 = Wsm + (64 + lane) * WPITCH;  // rows >= 80 are zero
    float a0 = 0.f, a1 = 0.f, a2 = 0.f;
#pragma unroll
    for (int k = 0; k < HH; k++) {
        a0 = fmaf(v[k], w0[k], a0);
        a1 = fmaf(v[k], w1[k], a1);
        a2 = fmaf(v[k], w2[k], a2);
    }
    float mu = warp_sum(a0 + a1 + a2) * (1.f / 80.f);
    float d0 = a0 - mu, d1 = a1 - mu, d2 = v2 ? (a2 - mu) : 0.f;
    float var = warp_sum(fmaf(d0, d0, fmaf(d1, d1, d2 * d2))) * (1.f / 79.f);
    float inv = 1.f / (sqrtf(var) + LN_EPS);
    gbuf[lane]      = d0 * inv * gi[lane]      + bi[lane]      + bh[lane];
    gbuf[32 + lane] = d1 * inv * gi[32 + lane] + bi[32 + lane] + bh[32 + lane];
    if (v2)
        gbuf[64 + lane] = d2 * inv * gi[64 + lane] + bi[64 + lane] + bh[64 + lane];
    __syncwarp();
    float c = 0.f, ov = 0.f;
    if (act) {
        float iv = gbuf[lane];
        ov = gbuf[40 + lane];
        float gv = gbuf[60 + lane];
        c = fast_sigmoid(iv) * fast_tanh(gv);
    }
    __syncwarp();
    float mu2 = warp_sum(c) * (1.f / 20.f);
    float dc = act ? (c - mu2) : 0.f;
    float var2 = warp_sum(dc * dc) * (1.f / 19.f);
    float inv2 = 1.f / (sqrtf(var2) + LN_EPS);
    float h = 0.f;
    if (act) {
        float cn = dc * inv2 * go[lane] + bo[lane];
        h = fast_sigmoid(ov) * fast_tanh(cn);
    }
    return h;
}

__global__ void __launch_bounds__(32 * BUILD_WARPS)
build_table_kernel(Weights w) {
    __shared__ float Wih0_s[WROWS * WPITCH];
    __shared__ float Wih1_s[WROWS * WPITCH];
    __shared__ float gates_s[BUILD_WARPS][GG];
    __shared__ float hx_s[BUILD_WARPS][HH];

    int tid = threadIdx.x;
    for (int idx = tid; idx < WROWS * WPITCH; idx += blockDim.x) {
        int r = idx / WPITCH, k = idx - r * WPITCH;
        float v0 = 0.f, v1 = 0.f;
        if (r < GG && k < HH) { v0 = w.Wih0[r * HH + k]; v1 = w.Wih1[r * HH + k]; }
        Wih0_s[idx] = v0;
        Wih1_s[idx] = v1;
    }
    __syncthreads();

    int warp = tid >> 5, lane = tid & 31;
    int entry = blockIdx.x * BUILD_WARPS + warp;
    float x = fmaf((float)entry, TAB_STEP, TAB_XMIN);
    const bool act = lane < HH;

    // layer 1
    float hval = 0.f;
    if (act) hval = fmaf(x, w.W1[lane], w.b1[lane]);
    {
        float mu = warp_sum(act ? hval : 0.f) * (1.f / 20.f);
        float d = act ? (hval - mu) : 0.f;
        float var = warp_sum(d * d) * (1.f / 19.f);
        float inv = 1.f / (sqrtf(var) + LN_EPS);
        if (act) hval = fast_tanh(d * inv * w.g1[lane] + w.be1[lane]);
    }

    float v[HH];
    if (act) hx_s[warp][lane] = hval;
    __syncwarp();
#pragma unroll
    for (int k = 0; k < HH; k++) v[k] = hx_s[warp][k];
    __syncwarp();

    hval = cell_warp(v, Wih0_s, w.gi0, w.bi0, w.bh0, w.go0, w.bo0,
                     gates_s[warp], lane);

    if (act) hx_s[warp][lane] = hval;
    __syncwarp();
#pragma unroll
    for (int k = 0; k < HH; k++) v[k] = hx_s[warp][k];
    __syncwarp();

    hval = cell_warp(v, Wih1_s, w.gi1, w.bi1, w.bh1, w.go1, w.bo1,
                     gates_s[warp], lane);

    float p = act ? hval * w.Wout[lane] : 0.f;
    p = warp_sum(p);
    if (lane == 0) {
        float val = p + w.bout[0];
        g_tab2[entry].x = val;
        if (entry > 0) g_tab2[entry - 1].y = val;
        if (entry == TAB_N - 1) g_tab2[entry].y = val;   // defined, never read
    }
}

// ===================== kernel 2: smem-table linear interpolation ============
__device__ __forceinline__ float interp_one_s(float x, const float2* tab_s) {
    x = fminf(fmaxf(x, TAB_XMIN), TAB_XMAX);
    float t = (x - TAB_XMIN) * TAB_INV_STEP;
    int i = __float2int_rd(t);
    i = min(i, TAB_N - 2);
    float s = t - (float)i;
    float2 q = tab_s[i];                  // one LDS.64 (random banks)
    return fmaf(s, q.y - q.x, q.x);
}

#define VPT 8   // float4s per thread (front-batched -> MLP=8)

__global__ void __launch_bounds__(256)
interp_kernel(const float4* __restrict__ x4, float4* __restrict__ o4, int n4,
              const float* __restrict__ x, float* __restrict__ out, int n) {
    __shared__ float2 tab_s[TAB_N];

    // stage the table: 32KB, coalesced float4 loads
    {
        const float4* src = (const float4*)g_tab2;
        float4* dst = (float4*)tab_s;
#pragma unroll
        for (int j = 0; j < TAB_N / 2 / 256; j++)
            dst[threadIdx.x + j * 256] = src[threadIdx.x + j * 256];
    }
    __syncthreads();

    int base = blockIdx.x * (256 * VPT) + threadIdx.x;

    if (base + (VPT - 1) * 256 < n4) {           // hot: full block, no guards
        float4 xv[VPT];
#pragma unroll
        for (int j = 0; j < VPT; j++) xv[j] = __ldcs(&x4[base + j * 256]);
#pragma unroll
        for (int j = 0; j < VPT; j++) {
            float4 ov;
            ov.x = interp_one_s(xv[j].x, tab_s);
            ov.y = interp_one_s(xv[j].y, tab_s);
            ov.z = interp_one_s(xv[j].z, tab_s);
            ov.w = interp_one_s(xv[j].w, tab_s);
            __stcs(&o4[base + j * 256], ov);
        }
    } else {                                      // edge block
#pragma unroll
        for (int j = 0; j < VPT; j++) {
            int idx = base + j * 256;
            if (idx < n4) {
                float4 xv = __ldcs(&x4[idx]);
                float4 ov;
                ov.x = interp_one_s(xv.x, tab_s);
                ov.y = interp_one_s(xv.y, tab_s);
                ov.z = interp_one_s(xv.z, tab_s);
                ov.w = interp_one_s(xv.w, tab_s);
                __stcs(&o4[idx], ov);
            }
        }
        // n % 4 tail
        if (blockIdx.x == gridDim.x - 1 && threadIdx.x < 32) {
            for (int i = n4 * 4 + threadIdx.x; i < n; i += 32)
                out[i] = interp_one_s(x[i], tab_s);
        }
    }
}

extern "C" void kernel_launch(void* const* d_in, const int* in_sizes, int n_in,
                              void* d_out, int out_size) {
    Weights w;
    w.W1 = (const float*)d_in[1];
    w.b1 = (const float*)d_in[2];
    w.g1 = (const float*)d_in[3];
    w.be1 = (const float*)d_in[4];
    w.Wih0 = (const float*)d_in[5];
    w.gi0 = (const float*)d_in[7];
    w.bi0 = (const float*)d_in[8];
    w.bh0 = (const float*)d_in[10];
    w.go0 = (const float*)d_in[11];
    w.bo0 = (const float*)d_in[12];
    w.Wih1 = (const float*)d_in[13];
    w.gi1 = (const float*)d_in[15];
    w.bi1 = (const float*)d_in[16];
    w.bh1 = (const float*)d_in[18];
    w.go1 = (const float*)d_in[19];
    w.bo1 = (const float*)d_in[20];
    w.Wout = (const float*)d_in[21];
    w.bout = (const float*)d_in[22];

    const float* x = (const float*)d_in[0];
    float* out = (float*)d_out;
    int n = in_sizes[0];
    int n4 = n / 4;

    build_table_kernel<<<TAB_N / BUILD_WARPS, 32 * BUILD_WARPS>>>(w);

    int per_block = 256 * VPT;
    int blocks = (n4 + per_block - 1) / per_block;
    if (blocks == 0) blocks = 1;
    interp_kernel<<<blocks, 256>>>((const float4*)x, (float4*)out, n4, x, out, n);
}

// round 7
// speedup vs baseline: 1.4608x; 1.1175x over previous
#include <cuda_runtime.h>
#include <math.h>

// out[i] = F(x[i]) for a fixed smooth scalar F (weights shared across elems).
// Kernel 1: warp-per-entry exact tabulation of F on [-6.5, 6.5] (2048 nodes),
//           stored as overlapping float2 pairs {tab[j], tab[j+1]}.
// Kernel 2: streaming LINEAR interpolation, 16KB table staged in shared
//           memory, grid sized so all CTAs are resident in ONE wave.

#define HH 20
#define GG 80
#define LN_EPS 1e-5f

#define TAB_N 2048
#define TAB_XMIN (-6.5f)
#define TAB_XMAX (6.5f)
#define TAB_STEP ((TAB_XMAX - TAB_XMIN) / (float)(TAB_N - 1))
#define TAB_INV_STEP ((float)(TAB_N - 1) / (TAB_XMAX - TAB_XMIN))
// t = x*TAB_INV_STEP + TAB_T_OFF, clamped to [0, TAB_N-1 - ulp]
#define TAB_T_OFF (-(TAB_XMIN) * TAB_INV_STEP)
#define TAB_T_MAX ((float)(TAB_N - 1) - 0.001f)

__device__ float2 g_tab2[TAB_N];   // g_tab2[j] = {tab[j], tab[j+1]}

struct Weights {
    const float *W1, *b1, *g1, *be1;
    const float *Wih0, *gi0, *bi0, *bh0, *go0, *bo0;
    const float *Wih1, *gi1, *bi1, *bh1, *go1, *bo1;
    const float *Wout, *bout;
};

__device__ __forceinline__ float fast_sigmoid(float z) {
    return 1.0f / (1.0f + __expf(-z));
}
__device__ __forceinline__ float fast_tanh(float z) {
    return 1.0f - 2.0f / (1.0f + __expf(2.0f * z));
}
__device__ __forceinline__ float warp_sum(float v) {
#pragma unroll
    for (int off = 16; off; off >>= 1) v += __shfl_xor_sync(0xffffffffu, v, off);
    return v;
}

// ===================== kernel 1: warp-per-entry table build =================
#define BUILD_WARPS 16
#define WPITCH 21
#define WROWS  96

__device__ __forceinline__ float cell_warp(const float* __restrict__ v,
                                           const float* __restrict__ Wsm,
                                           const float* gi, const float* bi,
                                           const float* bh, const float* go,
                                           const float* bo, float* gbuf,
                                           int lane) {
    const bool v2 = lane < 16;
    const bool act = lane < HH;
    const float* w0 = Wsm + lane * WPITCH;
    const float* w1 = Wsm + (32 + lane) * WPITCH;
    const float* w2 = Wsm + (64 + lane) * WPITCH;  // rows >= 80 are zero
    float a0 = 0.f, a1 = 0.f, a2 = 0.f;
#pragma unroll
    for (int k = 0; k < HH; k++) {
        a0 = fmaf(v[k], w0[k], a0);
        a1 = fmaf(v[k], w1[k], a1);
        a2 = fmaf(v[k], w2[k], a2);
    }
    float mu = warp_sum(a0 + a1 + a2) * (1.f / 80.f);
    float d0 = a0 - mu, d1 = a1 - mu, d2 = v2 ? (a2 - mu) : 0.f;
    float var = warp_sum(fmaf(d0, d0, fmaf(d1, d1, d2 * d2))) * (1.f / 79.f);
    float inv = 1.f / (sqrtf(var) + LN_EPS);
    gbuf[lane]      = d0 * inv * gi[lane]      + bi[lane]      + bh[lane];
    gbuf[32 + lane] = d1 * inv * gi[32 + lane] + bi[32 + lane] + bh[32 + lane];
    if (v2)
        gbuf[64 + lane] = d2 * inv * gi[64 + lane] + bi[64 + lane] + bh[64 + lane];
    __syncwarp();
    float c = 0.f, ov = 0.f;
    if (act) {
        float iv = gbuf[lane];
        ov = gbuf[40 + lane];
        float gv = gbuf[60 + lane];
        c = fast_sigmoid(iv) * fast_tanh(gv);
    }
    __syncwarp();
    float mu2 = warp_sum(c) * (1.f / 20.f);
    float dc = act ? (c - mu2) : 0.f;
    float var2 = warp_sum(dc * dc) * (1.f / 19.f);
    float inv2 = 1.f / (sqrtf(var2) + LN_EPS);
    float h = 0.f;
    if (act) {
        float cn = dc * inv2 * go[lane] + bo[lane];
        h = fast_sigmoid(ov) * fast_tanh(cn);
    }
    return h;
}

__global__ void __launch_bounds__(32 * BUILD_WARPS)
build_table_kernel(Weights w) {
    __shared__ float Wih0_s[WROWS * WPITCH];
    __shared__ float Wih1_s[WROWS * WPITCH];
    __shared__ float gates_s[BUILD_WARPS][GG];
    __shared__ float hx_s[BUILD_WARPS][HH];

    int tid = threadIdx.x;
    for (int idx = tid; idx < WROWS * WPITCH; idx += blockDim.x) {
        int r = idx / WPITCH, k = idx - r * WPITCH;
        float v0 = 0.f, v1 = 0.f;
        if (r < GG && k < HH) { v0 = w.Wih0[r * HH + k]; v1 = w.Wih1[r * HH + k]; }
        Wih0_s[idx] = v0;
        Wih1_s[idx] = v1;
    }
    __syncthreads();

    int warp = tid >> 5, lane = tid & 31;
    int entry = blockIdx.x * BUILD_WARPS + warp;
    float x = fmaf((float)entry, TAB_STEP, TAB_XMIN);
    const bool act = lane < HH;

    // layer 1
    float hval = 0.f;
    if (act) hval = fmaf(x, w.W1[lane], w.b1[lane]);
    {
        float mu = warp_sum(act ? hval : 0.f) * (1.f / 20.f);
        float d = act ? (hval - mu) : 0.f;
        float var = warp_sum(d * d) * (1.f / 19.f);
        float inv = 1.f / (sqrtf(var) + LN_EPS);
        if (act) hval = fast_tanh(d * inv * w.g1[lane] + w.be1[lane]);
    }

    float v[HH];
    if (act) hx_s[warp][lane] = hval;
    __syncwarp();
#pragma unroll
    for (int k = 0; k < HH; k++) v[k] = hx_s[warp][k];
    __syncwarp();

    hval = cell_warp(v, Wih0_s, w.gi0, w.bi0, w.bh0, w.go0, w.bo0,
                     gates_s[warp], lane);

    if (act) hx_s[warp][lane] = hval;
    __syncwarp();
#pragma unroll
    for (int k = 0; k < HH; k++) v[k] = hx_s[warp][k];
    __syncwarp();

    hval = cell_warp(v, Wih1_s, w.gi1, w.bi1, w.bh1, w.go1, w.bo1,
                     gates_s[warp], lane);

    float p = act ? hval * w.Wout[lane] : 0.f;
    p = warp_sum(p);
    if (lane == 0) {
        float val = p + w.bout[0];
        g_tab2[entry].x = val;
        if (entry > 0) g_tab2[entry - 1].y = val;
        if (entry == TAB_N - 1) g_tab2[entry].y = val;   // defined, never read
    }
}

// ===================== kernel 2: smem-table linear interpolation ============
__device__ __forceinline__ float interp_one_s(float x, const float2* tab_s) {
    float t = fmaf(x, TAB_INV_STEP, TAB_T_OFF);
    t = fminf(fmaxf(t, 0.0f), TAB_T_MAX);      // clamp in t-space
    int i = __float2int_rd(t);
    float s = t - (float)i;
    float2 q = tab_s[i];                        // one LDS.64 (random banks)
    return fmaf(s, q.y - q.x, q.x);
}

#define VPT 4   // float4s per thread (front-batched -> MLP=4)

__global__ void __launch_bounds__(256)
interp_kernel(const float4* __restrict__ x4, float4* __restrict__ o4, int n4,
              const float* __restrict__ x, float* __restrict__ out, int n) {
    __shared__ float2 tab_s[TAB_N];

    // stage the 16KB table: coalesced float4 loads (2 per thread)
    {
        const float4* src = (const float4*)g_tab2;
        float4* dst = (float4*)tab_s;
#pragma unroll
        for (int j = 0; j < TAB_N / 2 / 256; j++)
            dst[threadIdx.x + j * 256] = src[threadIdx.x + j * 256];
    }
    __syncthreads();

    int base = blockIdx.x * (256 * VPT) + threadIdx.x;

    if (base + (VPT - 1) * 256 < n4) {           // hot: full block, no guards
        float4 xv[VPT];
#pragma unroll
        for (int j = 0; j < VPT; j++) xv[j] = __ldcs(&x4[base + j * 256]);
#pragma unroll
        for (int j = 0; j < VPT; j++) {
            float4 ov;
            ov.x = interp_one_s(xv[j].x, tab_s);
            ov.y = interp_one_s(xv[j].y, tab_s);
            ov.z = interp_one_s(xv[j].z, tab_s);
            ov.w = interp_one_s(xv[j].w, tab_s);
            __stcs(&o4[base + j * 256], ov);
        }
    } else {                                      // edge block
#pragma unroll
        for (int j = 0; j < VPT; j++) {
            int idx = base + j * 256;
            if (idx < n4) {
                float4 xv = __ldcs(&x4[idx]);
                float4 ov;
                ov.x = interp_one_s(xv.x, tab_s);
                ov.y = interp_one_s(xv.y, tab_s);
                ov.z = interp_one_s(xv.z, tab_s);
                ov.w = interp_one_s(xv.w, tab_s);
                __stcs(&o4[idx], ov);
            }
        }
        // n % 4 tail
        if (blockIdx.x == gridDim.x - 1 && threadIdx.x < 32) {
            for (int i = n4 * 4 + threadIdx.x; i < n; i += 32)
                out[i] = interp_one_s(x[i], tab_s);
        }
    }
}

extern "C" void kernel_launch(void* const* d_in, const int* in_sizes, int n_in,
                              void* d_out, int out_size) {
    Weights w;
    w.W1 = (const float*)d_in[1];
    w.b1 = (const float*)d_in[2];
    w.g1 = (const float*)d_in[3];
    w.be1 = (const float*)d_in[4];
    w.Wih0 = (const float*)d_in[5];
    w.gi0 = (const float*)d_in[7];
    w.bi0 = (const float*)d_in[8];
    w.bh0 = (const float*)d_in[10];
    w.go0 = (const float*)d_in[11];
    w.bo0 = (const float*)d_in[12];
    w.Wih1 = (const float*)d_in[13];
    w.gi1 = (const float*)d_in[15];
    w.bi1 = (const float*)d_in[16];
    w.bh1 = (const float*)d_in[18];
    w.go1 = (const float*)d_in[19];
    w.bo1 = (const float*)d_in[20];
    w.Wout = (const float*)d_in[21];
    w.bout = (const float*)d_in[22];

    const float* x = (const float*)d_in[0];
    float* out = (float*)d_out;
    int n = in_sizes[0];
    int n4 = n / 4;

    build_table_kernel<<<TAB_N / BUILD_WARPS, 32 * BUILD_WARPS>>>(w);

    int per_block = 256 * VPT;
    int blocks = (n4 + per_block - 1) / per_block;
    if (blocks == 0) blocks = 1;
    interp_kernel<<<blocks, 256>>>((const float4*)x, (float4*)out, n4, x, out, n);
}

// round 8
// speedup vs baseline: 1.4858x; 1.0171x over previous
#include <cuda_runtime.h>
#include <math.h>

// out[i] = F(x[i]) for a fixed smooth scalar F (weights shared across elems).
// Kernel 1: warp-per-entry exact tabulation of F on [-6.5, 6.5] (1024 nodes),
//           stored as overlapping float2 pairs {tab[j], tab[j+1]}.
// Kernel 2: streaming LINEAR interpolation, 8KB table in shared memory,
//           grid = 1184 blocks (8 CTAs/SM, full residency), k-strided VPT=4.

#define HH 20
#define GG 80
#define LN_EPS 1e-5f

#define TAB_N 1024
#define TAB_XMIN (-6.5f)
#define TAB_XMAX (6.5f)
#define TAB_STEP ((TAB_XMAX - TAB_XMIN) / (float)(TAB_N - 1))
#define TAB_INV_STEP ((float)(TAB_N - 1) / (TAB_XMAX - TAB_XMIN))
#define TAB_T_OFF (-(TAB_XMIN) * TAB_INV_STEP)
#define TAB_T_MAX ((float)(TAB_N - 1) - 0.001f)

__device__ float2 g_tab2[TAB_N];   // g_tab2[j] = {tab[j], tab[j+1]}

struct Weights {
    const float *W1, *b1, *g1, *be1;
    const float *Wih0, *gi0, *bi0, *bh0, *go0, *bo0;
    const float *Wih1, *gi1, *bi1, *bh1, *go1, *bo1;
    const float *Wout, *bout;
};

__device__ __forceinline__ float fast_sigmoid(float z) {
    return 1.0f / (1.0f + __expf(-z));
}
__device__ __forceinline__ float fast_tanh(float z) {
    return 1.0f - 2.0f / (1.0f + __expf(2.0f * z));
}
__device__ __forceinline__ float warp_sum(float v) {
#pragma unroll
    for (int off = 16; off; off >>= 1) v += __shfl_xor_sync(0xffffffffu, v, off);
    return v;
}

// ===================== kernel 1: warp-per-entry table build =================
#define BUILD_WARPS 4
#define WPITCH 21
#define WROWS  96

__device__ __forceinline__ float cell_warp(const float* __restrict__ v,
                                           const float* __restrict__ Wsm,
                                           const float* gi, const float* bi,
                                           const float* bh, const float* go,
                                           const float* bo, float* gbuf,
                                           int lane) {
    const bool v2 = lane < 16;
    const bool act = lane < HH;
    const float* w0 = Wsm + lane * WPITCH;
    const float* w1 = Wsm + (32 + lane) * WPITCH;
    const float* w2 = Wsm + (64 + lane) * WPITCH;  // rows >= 80 are zero
    float a0 = 0.f, a1 = 0.f, a2 = 0.f;
#pragma unroll
    for (int k = 0; k < HH; k++) {
        a0 = fmaf(v[k], w0[k], a0);
        a1 = fmaf(v[k], w1[k], a1);
        a2 = fmaf(v[k], w2[k], a2);
    }
    float mu = warp_sum(a0 + a1 + a2) * (1.f / 80.f);
    float d0 = a0 - mu, d1 = a1 - mu, d2 = v2 ? (a2 - mu) : 0.f;
    float var = warp_sum(fmaf(d0, d0, fmaf(d1, d1, d2 * d2))) * (1.f / 79.f);
    float inv = 1.f / (sqrtf(var) + LN_EPS);
    gbuf[lane]      = d0 * inv * gi[lane]      + bi[lane]      + bh[lane];
    gbuf[32 + lane] = d1 * inv * gi[32 + lane] + bi[32 + lane] + bh[32 + lane];
    if (v2)
        gbuf[64 + lane] = d2 * inv * gi[64 + lane] + bi[64 + lane] + bh[64 + lane];
    __syncwarp();
    float c = 0.f, ov = 0.f;
    if (act) {
        float iv = gbuf[lane];
        ov = gbuf[40 + lane];
        float gv = gbuf[60 + lane];
        c = fast_sigmoid(iv) * fast_tanh(gv);
    }
    __syncwarp();
    float mu2 = warp_sum(c) * (1.f / 20.f);
    float dc = act ? (c - mu2) : 0.f;
    float var2 = warp_sum(dc * dc) * (1.f / 19.f);
    float inv2 = 1.f / (sqrtf(var2) + LN_EPS);
    float h = 0.f;
    if (act) {
        float cn = dc * inv2 * go[lane] + bo[lane];
        h = fast_sigmoid(ov) * fast_tanh(cn);
    }
    return h;
}

__global__ void __launch_bounds__(32 * BUILD_WARPS)
build_table_kernel(Weights w) {
    __shared__ float Wih0_s[WROWS * WPITCH];
    __shared__ float Wih1_s[WROWS * WPITCH];
    __shared__ float gates_s[BUILD_WARPS][GG];
    __shared__ float hx_s[BUILD_WARPS][HH];

    int tid = threadIdx.x;
    for (int idx = tid; idx < WROWS * WPITCH; idx += blockDim.x) {
        int r = idx / WPITCH, k = idx - r * WPITCH;
        float v0 = 0.f, v1 = 0.f;
        if (r < GG && k < HH) { v0 = w.Wih0[r * HH + k]; v1 = w.Wih1[r * HH + k]; }
        Wih0_s[idx] = v0;
        Wih1_s[idx] = v1;
    }
    __syncthreads();

    int warp = tid >> 5, lane = tid & 31;
    int entry = blockIdx.x * BUILD_WARPS + warp;
    float x = fmaf((float)entry, TAB_STEP, TAB_XMIN);
    const bool act = lane < HH;

    // layer 1
    float hval = 0.f;
    if (act) hval = fmaf(x, w.W1[lane], w.b1[lane]);
    {
        float mu = warp_sum(act ? hval : 0.f) * (1.f / 20.f);
        float d = act ? (hval - mu) : 0.f;
        float var = warp_sum(d * d) * (1.f / 19.f);
        float inv = 1.f / (sqrtf(var) + LN_EPS);
        if (act) hval = fast_tanh(d * inv * w.g1[lane] + w.be1[lane]);
    }

    float v[HH];
    if (act) hx_s[warp][lane] = hval;
    __syncwarp();
#pragma unroll
    for (int k = 0; k < HH; k++) v[k] = hx_s[warp][k];
    __syncwarp();

    hval = cell_warp(v, Wih0_s, w.gi0, w.bi0, w.bh0, w.go0, w.bo0,
                     gates_s[warp], lane);

    if (act) hx_s[warp][lane] = hval;
    __syncwarp();
#pragma unroll
    for (int k = 0; k < HH; k++) v[k] = hx_s[warp][k];
    __syncwarp();

    hval = cell_warp(v, Wih1_s, w.gi1, w.bi1, w.bh1, w.go1, w.bo1,
                     gates_s[warp], lane);

    float p = act ? hval * w.Wout[lane] : 0.f;
    p = warp_sum(p);
    if (lane == 0) {
        float val = p + w.bout[0];
        g_tab2[entry].x = val;
        if (entry > 0) g_tab2[entry - 1].y = val;
        if (entry == TAB_N - 1) g_tab2[entry].y = val;   // defined, never read
    }
}

// ===================== kernel 2: smem-table linear interpolation ============
__device__ __forceinline__ float interp_one_s(float x, const float2* tab_s) {
    float t = fmaf(x, TAB_INV_STEP, TAB_T_OFF);
    t = fminf(fmaxf(t, 0.0f), TAB_T_MAX);      // clamp in t-space
    int i = __float2int_rd(t);
    float s = t - (float)i;
    float2 q = tab_s[i];                        // one LDS.64 (random banks)
    return fmaf(s, q.y - q.x, q.x);
}

#define VPT 4          // k-strided float4 batches per thread
#define IBLOCKS 1184   // 8 CTAs/SM x 148 SMs -> full residency in one wave

__global__ void __launch_bounds__(256)
interp_kernel(const float4* __restrict__ x4, float4* __restrict__ o4, int n4,
              const float* __restrict__ x, float* __restrict__ out, int n) {
    __shared__ float2 tab_s[TAB_N];

    int gtid = blockIdx.x * 256 + threadIdx.x;
    int stride = gridDim.x * 256;

    // 1) front-batch the global x loads (independent of the table)
    float4 xv[VPT];
    bool vld[VPT];
#pragma unroll
    for (int k = 0; k < VPT; k++) {
        int idx = gtid + k * stride;
        vld[k] = idx < n4;
        if (vld[k]) xv[k] = __ldcs(&x4[idx]);
    }

    // 2) stage the 8KB table (coalesced float4, 2 per thread)
    {
        const float4* src = (const float4*)g_tab2;
        float4* dst = (float4*)tab_s;
#pragma unroll
        for (int j = 0; j < TAB_N / 2 / 256; j++)
            dst[threadIdx.x + j * 256] = src[threadIdx.x + j * 256];
    }
    __syncthreads();

    // 3) interpolate + stream out
#pragma unroll
    for (int k = 0; k < VPT; k++) {
        if (!vld[k]) continue;
        float4 ov;
        ov.x = interp_one_s(xv[k].x, tab_s);
        ov.y = interp_one_s(xv[k].y, tab_s);
        ov.z = interp_one_s(xv[k].z, tab_s);
        ov.w = interp_one_s(xv[k].w, tab_s);
        __stcs(&o4[gtid + k * stride], ov);
    }

    // n % 4 tail
    if (blockIdx.x == 0 && threadIdx.x < 32) {
        for (int i = n4 * 4 + threadIdx.x; i < n; i += 32)
            out[i] = interp_one_s(x[i], tab_s);
    }
}

extern "C" void kernel_launch(void* const* d_in, const int* in_sizes, int n_in,
                              void* d_out, int out_size) {
    Weights w;
    w.W1 = (const float*)d_in[1];
    w.b1 = (const float*)d_in[2];
    w.g1 = (const float*)d_in[3];
    w.be1 = (const float*)d_in[4];
    w.Wih0 = (const float*)d_in[5];
    w.gi0 = (const float*)d_in[7];
    w.bi0 = (const float*)d_in[8];
    w.bh0 = (const float*)d_in[10];
    w.go0 = (const float*)d_in[11];
    w.bo0 = (const float*)d_in[12];
    w.Wih1 = (const float*)d_in[13];
    w.gi1 = (const float*)d_in[15];
    w.bi1 = (const float*)d_in[16];
    w.bh1 = (const float*)d_in[18];
    w.go1 = (const float*)d_in[19];
    w.bo1 = (const float*)d_in[20];
    w.Wout = (const float*)d_in[21];
    w.bout = (const float*)d_in[22];

    const float* x = (const float*)d_in[0];
    float* out = (float*)d_out;
    int n = in_sizes[0];
    int n4 = n / 4;

    build_table_kernel<<<TAB_N / BUILD_WARPS, 32 * BUILD_WARPS>>>(w);

    // enough blocks to cover n4 with VPT strided batches, capped at IBLOCKS
    long long need = ((long long)n4 + 256LL * VPT - 1) / (256LL * VPT);
    int blocks = (int)((need < IBLOCKS) ? (need ? need : 1) : IBLOCKS);
    // ensure stride coverage: blocks*256*VPT >= n4 always true when blocks==IBLOCKS?
    // IBLOCKS*256*4 = 1,212,416 >= n4 (1,000,000) holds for this problem; the
    // guards make any n safe because k-strides cover [0, blocks*256*VPT).
    if ((long long)blocks * 256 * VPT < n4) blocks = (int)need;  // safety
    interp_kernel<<<blocks, 256>>>((const float4*)x, (float4*)out, n4, x, out, n);
}